// round 2
// baseline (speedup 1.0000x reference)
#include <cuda_runtime.h>
#include <cstdint>

#define N_NODES 100000
#define N_EDGES 1600000
#define HID     128
#define IN_DIM  16
#define LN_EPS  1e-5f
#define SCAN_B  512

// ---------------- device scratch (no allocation allowed) ----------------
__device__ int   g_deg[N_NODES];                 // counts, then CSR cursor
__device__ float g_dis[N_NODES];                 // rsqrt(deg)
__device__ int   g_off[N_NODES + 1];             // CSR row offsets
__device__ int2  g_csr[N_EDGES];                 // (src, float_bits(dis[src]))
__device__ float g_h[(size_t)N_NODES * HID];     // node features
__device__ float g_p[(size_t)N_NODES * HID];     // propagated features
__device__ int   g_bsum[256];                    // block sums for scan
__device__ int   g_wide;                         // 1 = int64 edge_index, 0 = int32

// ---------------- edge dtype detection ----------------
// If edge_index is int64 (little-endian), every odd 32-bit word of the first
// 2048 edges is a zero high-half. For int32 random values in [0,1e5) that is
// astronomically unlikely.
__global__ void k_detect(const unsigned int* __restrict__ e32, int nwords) {
    __shared__ unsigned int s_or;
    if (threadIdx.x == 0) s_or = 0u;
    __syncthreads();
    unsigned int v = 0u;
    for (int i = threadIdx.x * 2 + 1; i < nwords; i += blockDim.x * 2) v |= e32[i];
    atomicOr(&s_or, v);
    __syncthreads();
    if (threadIdx.x == 0) g_wide = (s_or == 0u) ? 1 : 0;
}

__device__ __forceinline__ int load_edge(const void* eidx, long idx, int wide) {
    if (wide) return (int)((const long long*)eidx)[idx];
    return ((const int*)eidx)[idx];
}

// ---------------- degree histogram + CSR build ----------------
__global__ void k_zero() {
    int i = blockIdx.x * blockDim.x + threadIdx.x;
    if (i < N_NODES) g_deg[i] = 0;
}

__global__ void k_hist(const void* __restrict__ eidx, int E) {
    int i = blockIdx.x * blockDim.x + threadIdx.x;
    if (i >= E) return;
    int wide = g_wide;
    int d = load_edge(eidx, (long)E + i, wide);
    atomicAdd(&g_deg[d], 1);
}

__global__ void k_scan1() {  // per-block reduction of degrees
    __shared__ int s[SCAN_B];
    int tid = threadIdx.x;
    int i = blockIdx.x * SCAN_B + tid;
    s[tid] = (i < N_NODES) ? g_deg[i] : 0;
    __syncthreads();
    for (int o = SCAN_B / 2; o > 0; o >>= 1) {
        if (tid < o) s[tid] += s[tid + o];
        __syncthreads();
    }
    if (tid == 0) g_bsum[blockIdx.x] = s[0];
}

__global__ void k_scan2(int nb) {  // exclusive scan of block sums (1 block)
    __shared__ int s[256];
    int tid = threadIdx.x;
    int v = (tid < nb) ? g_bsum[tid] : 0;
    s[tid] = v;
    __syncthreads();
    for (int o = 1; o < 256; o <<= 1) {
        int t = (tid >= o) ? s[tid - o] : 0;
        __syncthreads();
        s[tid] += t;
        __syncthreads();
    }
    if (tid < nb) g_bsum[tid] = s[tid] - v;  // exclusive
}

__global__ void k_scan3() {  // local exclusive scan + block offset -> offsets, dis, cursor
    __shared__ int s[SCAN_B];
    int tid = threadIdx.x;
    int i = blockIdx.x * SCAN_B + tid;
    int v = (i < N_NODES) ? g_deg[i] : 0;
    s[tid] = v;
    __syncthreads();
    for (int o = 1; o < SCAN_B; o <<= 1) {
        int t = (tid >= o) ? s[tid - o] : 0;
        __syncthreads();
        s[tid] += t;
        __syncthreads();
    }
    int off = g_bsum[blockIdx.x] + s[tid] - v;  // exclusive prefix
    if (i < N_NODES) {
        g_off[i] = off;
        g_dis[i] = rsqrtf((float)(v + 1));  // +1 self-loop; deg >= 1
        if (i == N_NODES - 1) g_off[N_NODES] = off + v;
        g_deg[i] = off;  // becomes fill cursor
    }
}

__global__ void k_fill(const void* __restrict__ eidx, int E) {
    int i = blockIdx.x * blockDim.x + threadIdx.x;
    if (i >= E) return;
    int wide = g_wide;
    int sidx = load_edge(eidx, i, wide);
    int didx = load_edge(eidx, (long)E + i, wide);
    int pos = atomicAdd(&g_deg[didx], 1);
    g_csr[pos] = make_int2(sidx, __float_as_int(g_dis[sidx]));
}

// ---------------- input projection: h = x @ W_in + b_in ----------------
__global__ void k_proj(const float* __restrict__ x, const float* __restrict__ Win,
                       const float* __restrict__ bin) {
    __shared__ float sW[IN_DIM * HID];
    __shared__ float sx[8 * IN_DIM];
    int tid = threadIdx.x;  // 128 threads, one per output column
    for (int i = tid; i < IN_DIM * HID; i += 128) sW[i] = Win[i];
    int base = blockIdx.x * 8;
    {
        int n = tid / IN_DIM, k = tid % IN_DIM;
        int node = base + n;
        sx[tid] = (node < N_NODES) ? x[(size_t)node * IN_DIM + k] : 0.f;
    }
    __syncthreads();
    float bc = bin[tid];
    for (int n = 0; n < 8; n++) {
        int node = base + n;
        if (node >= N_NODES) break;
        float sum = bc;
#pragma unroll
        for (int k = 0; k < IN_DIM; k++) sum += sx[n * IN_DIM + k] * sW[k * HID + tid];
        g_h[(size_t)node * HID + tid] = sum;
    }
}

// ---------------- propagate: p[d] = dis[d]*(sum_s dis[s]*h[s]) + dis[d]^2*h[d] ----------------
__global__ void k_gather() {
    int warp = threadIdx.x >> 5, lane = threadIdx.x & 31;
    int d = blockIdx.x * 8 + warp;
    if (d >= N_NODES) return;
    int start = g_off[d], end = g_off[d + 1];
    float dd = g_dis[d];
    const float4* hv = (const float4*)g_h;
    float4 acc = hv[(size_t)d * 32 + lane];  // self term (weight dd applied by final scale)
    acc.x *= dd; acc.y *= dd; acc.z *= dd; acc.w *= dd;
    for (int j = start; j < end; j += 32) {
        int2 ew = make_int2(0, 0);
        if (j + lane < end) ew = g_csr[j + lane];
        int cnt = min(32, end - j);
        for (int t = 0; t < cnt; t++) {
            int   s = __shfl_sync(0xffffffffu, ew.x, t);
            float w = __int_as_float(__shfl_sync(0xffffffffu, ew.y, t));
            float4 v = hv[(size_t)s * 32 + lane];
            acc.x += w * v.x; acc.y += w * v.y; acc.z += w * v.z; acc.w += w * v.w;
        }
    }
    acc.x *= dd; acc.y *= dd; acc.z *= dd; acc.w *= dd;
    ((float4*)g_p)[(size_t)d * 32 + lane] = acc;
}

// ---------------- transform: out = relu(LN(p@W + b)) [+ h_prev] ----------------
// block = 256 threads = 8 warps; each warp computes 8 rows x 128 cols (4 cols/lane).
// smem: W (64KB) + p tile 64x128 (32KB) = 96KB dynamic.
__global__ void k_transform(const float* __restrict__ W, const float* __restrict__ bias,
                            const float* __restrict__ gamma, const float* __restrict__ beta,
                            float* __restrict__ out, int add_res) {
    extern __shared__ float smem[];
    float* sW = smem;                 // 128*128
    float* sP = smem + HID * HID;     // 64*128
    int tid = threadIdx.x;
    float4* sW4 = (float4*)sW;
    const float4* W4 = (const float4*)W;
    for (int i = tid; i < HID * 32; i += 256) sW4[i] = W4[i];
    int rbase = blockIdx.x * 64;
    float4* sP4 = (float4*)sP;
    const float4* p4 = (const float4*)g_p;
    for (int i = tid; i < 64 * 32; i += 256) {
        int r = i >> 5;
        int node = rbase + r;
        sP4[i] = (node < N_NODES) ? p4[(size_t)node * 32 + (i & 31)] : make_float4(0, 0, 0, 0);
    }
    __syncthreads();

    int warp = tid >> 5, lane = tid & 31;
    int r0 = warp * 8;
    float4 acc[8];
#pragma unroll
    for (int r = 0; r < 8; r++) acc[r] = make_float4(0, 0, 0, 0);

    for (int k = 0; k < HID; k++) {
        float4 w4 = sW4[k * 32 + lane];
#pragma unroll
        for (int r = 0; r < 8; r++) {
            float pv = sP[(r0 + r) * HID + k];
            acc[r].x += pv * w4.x;
            acc[r].y += pv * w4.y;
            acc[r].z += pv * w4.z;
            acc[r].w += pv * w4.w;
        }
    }

    float4 bb = ((const float4*)bias)[lane];
    float4 gg = ((const float4*)gamma)[lane];
    float4 be = ((const float4*)beta)[lane];

#pragma unroll
    for (int r = 0; r < 8; r++) {
        int node = rbase + r0 + r;
        float4 a = acc[r];
        a.x += bb.x; a.y += bb.y; a.z += bb.z; a.w += bb.w;
        float s = a.x + a.y + a.z + a.w;
#pragma unroll
        for (int o = 16; o > 0; o >>= 1) s += __shfl_xor_sync(0xffffffffu, s, o);
        float mu = s * (1.f / 128.f);
        float dx = a.x - mu, dy = a.y - mu, dz = a.z - mu, dw = a.w - mu;
        float q = dx * dx + dy * dy + dz * dz + dw * dw;
#pragma unroll
        for (int o = 16; o > 0; o >>= 1) q += __shfl_xor_sync(0xffffffffu, q, o);
        float rstd = rsqrtf(q * (1.f / 128.f) + LN_EPS);
        float4 o4;
        o4.x = fmaxf(dx * rstd * gg.x + be.x, 0.f);
        o4.y = fmaxf(dy * rstd * gg.y + be.y, 0.f);
        o4.z = fmaxf(dz * rstd * gg.z + be.z, 0.f);
        o4.w = fmaxf(dw * rstd * gg.w + be.w, 0.f);
        if (node < N_NODES) {
            if (add_res) {
                float4 hp = ((const float4*)g_h)[(size_t)node * 32 + lane];
                o4.x += hp.x; o4.y += hp.y; o4.z += hp.z; o4.w += hp.w;
            }
            ((float4*)out)[(size_t)node * 32 + lane] = o4;
        }
    }
}

// ---------------- launch ----------------
extern "C" void kernel_launch(void* const* d_in, const int* in_sizes, int n_in,
                              void* d_out, int out_size) {
    const float* x   = (const float*)d_in[0];
    const void*  eix = d_in[1];  // int32 or int64, detected on device
    const float* Win = (const float*)d_in[2];
    const float* bin = (const float*)d_in[3];
    const float* Wc  = (const float*)d_in[4];  // [3,128,128]
    const float* bc  = (const float*)d_in[5];  // [3,128]
    const float* lg  = (const float*)d_in[6];  // [3,128]
    const float* lb  = (const float*)d_in[7];  // [3,128]
    int E = in_sizes[1] / 2;

    static bool attr_set = false;  // idempotent attribute set (not a work guard)
    if (!attr_set) {
        cudaFuncSetAttribute(k_transform, cudaFuncAttributeMaxDynamicSharedMemorySize,
                             (HID * HID + 64 * HID) * sizeof(float));
        attr_set = true;
    }

    void* h_addr = nullptr;
    cudaGetSymbolAddress(&h_addr, g_h);

    k_detect<<<1, 256>>>((const unsigned int*)eix, 4096);
    k_zero<<<(N_NODES + 255) / 256, 256>>>();
    k_hist<<<(E + 255) / 256, 256>>>(eix, E);
    int nb = (N_NODES + SCAN_B - 1) / SCAN_B;  // 196
    k_scan1<<<nb, SCAN_B>>>();
    k_scan2<<<1, 256>>>(nb);
    k_scan3<<<nb, SCAN_B>>>();
    k_fill<<<(E + 255) / 256, 256>>>(eix, E);

    k_proj<<<(N_NODES + 7) / 8, 128>>>(x, Win, bin);

    size_t tsmem = (HID * HID + 64 * HID) * sizeof(float);  // 96KB
    for (int l = 0; l < 3; l++) {
        k_gather<<<(N_NODES + 7) / 8, 256>>>();
        float* out = (l == 2) ? (float*)d_out : (float*)h_addr;
        k_transform<<<(N_NODES + 63) / 64, 256, tsmem>>>(
            Wc + (size_t)l * HID * HID, bc + l * HID, lg + l * HID, lb + l * HID,
            out, (l > 0) ? 1 : 0);
    }
}

// round 3
// speedup vs baseline: 1.0819x; 1.0819x over previous
#include <cuda_runtime.h>
#include <cstdint>

#define N_NODES 100000
#define N_EDGES 1600000
#define HID     128
#define IN_DIM  16
#define LN_EPS  1e-5f
#define SCAN_B  512

// ---------------- device scratch (no allocation allowed) ----------------
__device__ int   g_deg[N_NODES];                 // counts, then CSR cursor
__device__ float g_dis[N_NODES];                 // rsqrt(deg)
__device__ int   g_off[N_NODES + 1];             // CSR row offsets
__device__ int2  g_csr[N_EDGES];                 // (src, float_bits(dis[src]))
__device__ float g_h[(size_t)N_NODES * HID];     // node features
__device__ float g_p[(size_t)N_NODES * HID];     // propagated features
__device__ int   g_bsum[256];                    // block sums for scan
__device__ int   g_wide;                         // 1 = int64 edge_index, 0 = int32

// ---------------- packed f32x2 helpers ----------------
__device__ __forceinline__ void fma2(unsigned long long& d, unsigned long long a,
                                     unsigned long long b) {
    asm("fma.rn.f32x2 %0, %1, %2, %0;" : "+l"(d) : "l"(a), "l"(b));
}
__device__ __forceinline__ float2 unpack2(unsigned long long v) {
    float2 f;
    asm("mov.b64 {%0,%1}, %2;" : "=f"(f.x), "=f"(f.y) : "l"(v));
    return f;
}

// ---------------- edge dtype detection ----------------
__global__ void k_detect(const unsigned int* __restrict__ e32, int nwords) {
    __shared__ unsigned int s_or;
    if (threadIdx.x == 0) s_or = 0u;
    __syncthreads();
    unsigned int v = 0u;
    for (int i = threadIdx.x * 2 + 1; i < nwords; i += blockDim.x * 2) v |= e32[i];
    atomicOr(&s_or, v);
    __syncthreads();
    if (threadIdx.x == 0) g_wide = (s_or == 0u) ? 1 : 0;
}

__device__ __forceinline__ int load_edge(const void* eidx, long idx, int wide) {
    if (wide) return (int)((const long long*)eidx)[idx];
    return ((const int*)eidx)[idx];
}

// ---------------- degree histogram + CSR build ----------------
__global__ void k_zero() {
    int i = blockIdx.x * blockDim.x + threadIdx.x;
    if (i < N_NODES) g_deg[i] = 0;
}

__global__ void k_hist(const void* __restrict__ eidx, int E) {
    int i = blockIdx.x * blockDim.x + threadIdx.x;
    if (i >= E) return;
    int wide = g_wide;
    int d = load_edge(eidx, (long)E + i, wide);
    atomicAdd(&g_deg[d], 1);
}

__global__ void k_scan1() {
    __shared__ int s[SCAN_B];
    int tid = threadIdx.x;
    int i = blockIdx.x * SCAN_B + tid;
    s[tid] = (i < N_NODES) ? g_deg[i] : 0;
    __syncthreads();
    for (int o = SCAN_B / 2; o > 0; o >>= 1) {
        if (tid < o) s[tid] += s[tid + o];
        __syncthreads();
    }
    if (tid == 0) g_bsum[blockIdx.x] = s[0];
}

__global__ void k_scan2(int nb) {
    __shared__ int s[256];
    int tid = threadIdx.x;
    int v = (tid < nb) ? g_bsum[tid] : 0;
    s[tid] = v;
    __syncthreads();
    for (int o = 1; o < 256; o <<= 1) {
        int t = (tid >= o) ? s[tid - o] : 0;
        __syncthreads();
        s[tid] += t;
        __syncthreads();
    }
    if (tid < nb) g_bsum[tid] = s[tid] - v;
}

__global__ void k_scan3() {
    __shared__ int s[SCAN_B];
    int tid = threadIdx.x;
    int i = blockIdx.x * SCAN_B + tid;
    int v = (i < N_NODES) ? g_deg[i] : 0;
    s[tid] = v;
    __syncthreads();
    for (int o = 1; o < SCAN_B; o <<= 1) {
        int t = (tid >= o) ? s[tid - o] : 0;
        __syncthreads();
        s[tid] += t;
        __syncthreads();
    }
    int off = g_bsum[blockIdx.x] + s[tid] - v;
    if (i < N_NODES) {
        g_off[i] = off;
        g_dis[i] = rsqrtf((float)(v + 1));
        if (i == N_NODES - 1) g_off[N_NODES] = off + v;
        g_deg[i] = off;
    }
}

__global__ void k_fill(const void* __restrict__ eidx, int E) {
    int i = blockIdx.x * blockDim.x + threadIdx.x;
    if (i >= E) return;
    int wide = g_wide;
    int sidx = load_edge(eidx, i, wide);
    int didx = load_edge(eidx, (long)E + i, wide);
    int pos = atomicAdd(&g_deg[didx], 1);
    g_csr[pos] = make_int2(sidx, __float_as_int(g_dis[sidx]));
}

// ---------------- input projection: h = x @ W_in + b_in ----------------
__global__ void k_proj(const float* __restrict__ x, const float* __restrict__ Win,
                       const float* __restrict__ bin) {
    __shared__ float sW[IN_DIM * HID];
    __shared__ float sx[8 * IN_DIM];
    int tid = threadIdx.x;
    for (int i = tid; i < IN_DIM * HID; i += 128) sW[i] = Win[i];
    int base = blockIdx.x * 8;
    {
        int n = tid / IN_DIM, k = tid % IN_DIM;
        int node = base + n;
        sx[tid] = (node < N_NODES) ? x[(size_t)node * IN_DIM + k] : 0.f;
    }
    __syncthreads();
    float bc = bin[tid];
    for (int n = 0; n < 8; n++) {
        int node = base + n;
        if (node >= N_NODES) break;
        float sum = bc;
#pragma unroll
        for (int k = 0; k < IN_DIM; k++) sum += sx[n * IN_DIM + k] * sW[k * HID + tid];
        g_h[(size_t)node * HID + tid] = sum;
    }
}

// ---------------- propagate with MLP=4 unrolled gather ----------------
__global__ void k_gather() {
    int warp = threadIdx.x >> 5, lane = threadIdx.x & 31;
    int d = blockIdx.x * 8 + warp;
    if (d >= N_NODES) return;
    int start = g_off[d], end = g_off[d + 1];
    float dd = g_dis[d];
    const float4* hv = (const float4*)g_h;
    float4 acc = hv[(size_t)d * 32 + lane];
    acc.x *= dd; acc.y *= dd; acc.z *= dd; acc.w *= dd;
    for (int j = start; j < end; j += 32) {
        int2 ew = make_int2(0, 0);
        if (j + lane < end) ew = g_csr[j + lane];
        int cnt = min(32, end - j);
        int t = 0;
        for (; t + 4 <= cnt; t += 4) {
            int s0 = __shfl_sync(0xffffffffu, ew.x, t);
            int s1 = __shfl_sync(0xffffffffu, ew.x, t + 1);
            int s2 = __shfl_sync(0xffffffffu, ew.x, t + 2);
            int s3 = __shfl_sync(0xffffffffu, ew.x, t + 3);
            float w0 = __int_as_float(__shfl_sync(0xffffffffu, ew.y, t));
            float w1 = __int_as_float(__shfl_sync(0xffffffffu, ew.y, t + 1));
            float w2 = __int_as_float(__shfl_sync(0xffffffffu, ew.y, t + 2));
            float w3 = __int_as_float(__shfl_sync(0xffffffffu, ew.y, t + 3));
            float4 v0 = hv[(size_t)s0 * 32 + lane];
            float4 v1 = hv[(size_t)s1 * 32 + lane];
            float4 v2 = hv[(size_t)s2 * 32 + lane];
            float4 v3 = hv[(size_t)s3 * 32 + lane];
            acc.x += w0 * v0.x; acc.y += w0 * v0.y; acc.z += w0 * v0.z; acc.w += w0 * v0.w;
            acc.x += w1 * v1.x; acc.y += w1 * v1.y; acc.z += w1 * v1.z; acc.w += w1 * v1.w;
            acc.x += w2 * v2.x; acc.y += w2 * v2.y; acc.z += w2 * v2.z; acc.w += w2 * v2.w;
            acc.x += w3 * v3.x; acc.y += w3 * v3.y; acc.z += w3 * v3.z; acc.w += w3 * v3.w;
        }
        for (; t < cnt; t++) {
            int   s = __shfl_sync(0xffffffffu, ew.x, t);
            float w = __int_as_float(__shfl_sync(0xffffffffu, ew.y, t));
            float4 v = hv[(size_t)s * 32 + lane];
            acc.x += w * v.x; acc.y += w * v.y; acc.z += w * v.z; acc.w += w * v.w;
        }
    }
    acc.x *= dd; acc.y *= dd; acc.z *= dd; acc.w *= dd;
    ((float4*)g_p)[(size_t)d * 32 + lane] = acc;
}

// ---------------- transform: out = relu(LN(p@W + b)) [+ h_prev] ----------------
// f32x2 packed mainloop: acc lanes = (even-k partial, odd-k partial) per column.
// W staged in smem with k-rows pairwise interleaved: sW2[t*128 + c] = (W[2t][c], W[2t+1][c]).
__global__ void __launch_bounds__(256) k_transform(
        const float* __restrict__ W, const float* __restrict__ bias,
        const float* __restrict__ gamma, const float* __restrict__ beta,
        float* __restrict__ out, int add_res) {
    extern __shared__ float smem[];
    float* sWf = smem;                // 128*128 floats, pair-interleaved layout
    float* sP  = smem + HID * HID;    // 64*128
    int tid = threadIdx.x;

    // stage W with row-pair interleave (coalesced gmem reads)
    for (int i = tid; i < HID * HID; i += 256) {
        int k = i >> 7, c = i & 127;
        sWf[(((k >> 1) << 7) + c) * 2 + (k & 1)] = W[i];
    }
    int rbase = blockIdx.x * 64;
    float4* sP4 = (float4*)sP;
    const float4* p4 = (const float4*)g_p;
    for (int i = tid; i < 64 * 32; i += 256) {
        int r = i >> 5;
        int node = rbase + r;
        sP4[i] = (node < N_NODES) ? p4[(size_t)node * 32 + (i & 31)] : make_float4(0, 0, 0, 0);
    }
    __syncthreads();

    int warp = tid >> 5, lane = tid & 31;
    int r0 = warp * 8;
    const ulonglong2* sW2v = (const ulonglong2*)sWf;  // idx t*64 + pair

    unsigned long long acc[8][4];
#pragma unroll
    for (int r = 0; r < 8; r++)
#pragma unroll
        for (int c = 0; c < 4; c++) acc[r][c] = 0ull;

#pragma unroll 4
    for (int t = 0; t < 64; t++) {
        ulonglong2 wa = sW2v[t * 64 + lane * 2];      // cols 4l, 4l+1
        ulonglong2 wb = sW2v[t * 64 + lane * 2 + 1];  // cols 4l+2, 4l+3
#pragma unroll
        for (int r = 0; r < 8; r++) {
            unsigned long long pv =
                *(const unsigned long long*)(sP + (r0 + r) * HID + 2 * t);
            fma2(acc[r][0], pv, wa.x);
            fma2(acc[r][1], pv, wa.y);
            fma2(acc[r][2], pv, wb.x);
            fma2(acc[r][3], pv, wb.y);
        }
    }

    float4 bb = ((const float4*)bias)[lane];
    float4 gg = ((const float4*)gamma)[lane];
    float4 be = ((const float4*)beta)[lane];

#pragma unroll
    for (int r = 0; r < 8; r++) {
        int node = rbase + r0 + r;
        float2 e0 = unpack2(acc[r][0]);
        float2 e1 = unpack2(acc[r][1]);
        float2 e2 = unpack2(acc[r][2]);
        float2 e3 = unpack2(acc[r][3]);
        float4 a;
        a.x = e0.x + e0.y + bb.x;
        a.y = e1.x + e1.y + bb.y;
        a.z = e2.x + e2.y + bb.z;
        a.w = e3.x + e3.y + bb.w;
        float s = a.x + a.y + a.z + a.w;
#pragma unroll
        for (int o = 16; o > 0; o >>= 1) s += __shfl_xor_sync(0xffffffffu, s, o);
        float mu = s * (1.f / 128.f);
        float dx = a.x - mu, dy = a.y - mu, dz = a.z - mu, dw = a.w - mu;
        float q = dx * dx + dy * dy + dz * dz + dw * dw;
#pragma unroll
        for (int o = 16; o > 0; o >>= 1) q += __shfl_xor_sync(0xffffffffu, q, o);
        float rstd = rsqrtf(q * (1.f / 128.f) + LN_EPS);
        float4 o4;
        o4.x = fmaxf(dx * rstd * gg.x + be.x, 0.f);
        o4.y = fmaxf(dy * rstd * gg.y + be.y, 0.f);
        o4.z = fmaxf(dz * rstd * gg.z + be.z, 0.f);
        o4.w = fmaxf(dw * rstd * gg.w + be.w, 0.f);
        if (node < N_NODES) {
            if (add_res) {
                float4 hp = ((const float4*)g_h)[(size_t)node * 32 + lane];
                o4.x += hp.x; o4.y += hp.y; o4.z += hp.z; o4.w += hp.w;
            }
            ((float4*)out)[(size_t)node * 32 + lane] = o4;
        }
    }
}

// ---------------- launch ----------------
extern "C" void kernel_launch(void* const* d_in, const int* in_sizes, int n_in,
                              void* d_out, int out_size) {
    const float* x   = (const float*)d_in[0];
    const void*  eix = d_in[1];
    const float* Win = (const float*)d_in[2];
    const float* bin = (const float*)d_in[3];
    const float* Wc  = (const float*)d_in[4];
    const float* bc  = (const float*)d_in[5];
    const float* lg  = (const float*)d_in[6];
    const float* lb  = (const float*)d_in[7];
    int E = in_sizes[1] / 2;

    static bool attr_set = false;  // idempotent attribute set (not a work guard)
    if (!attr_set) {
        cudaFuncSetAttribute(k_transform, cudaFuncAttributeMaxDynamicSharedMemorySize,
                             (HID * HID + 64 * HID) * sizeof(float));
        attr_set = true;
    }

    void* h_addr = nullptr;
    cudaGetSymbolAddress(&h_addr, g_h);

    k_detect<<<1, 256>>>((const unsigned int*)eix, 4096);
    k_zero<<<(N_NODES + 255) / 256, 256>>>();
    k_hist<<<(E + 255) / 256, 256>>>(eix, E);
    int nb = (N_NODES + SCAN_B - 1) / SCAN_B;
    k_scan1<<<nb, SCAN_B>>>();
    k_scan2<<<1, 256>>>(nb);
    k_scan3<<<nb, SCAN_B>>>();
    k_fill<<<(E + 255) / 256, 256>>>(eix, E);

    k_proj<<<(N_NODES + 7) / 8, 128>>>(x, Win, bin);

    size_t tsmem = (HID * HID + 64 * HID) * sizeof(float);  // 96KB
    for (int l = 0; l < 3; l++) {
        k_gather<<<(N_NODES + 7) / 8, 256>>>();
        float* out = (l == 2) ? (float*)d_out : (float*)h_addr;
        k_transform<<<(N_NODES + 63) / 64, 256, tsmem>>>(
            Wc + (size_t)l * HID * HID, bc + l * HID, lg + l * HID, lb + l * HID,
            out, (l > 0) ? 1 : 0);
    }
}